// round 1
// baseline (speedup 1.0000x reference)
#include <cuda_runtime.h>
#include <cuda_fp16.h>
#include <math.h>

#define B_DIM 32
#define S_DIM 325
#define L_DIM 192
#define NSEQ (B_DIM * S_DIM)   // 10400
#define DH 128
#define NH 8
#define NEG_F (-1000000000.0f)

#define HPAD 34
#define HBUF (DH * HPAD)                 // floats per h buffer
#define QK_SMEM (131072 + 2*HBUF*4 + 2*32*4)   // 166144 bytes
#define ATTN_SMEM ((32*129 + 32*336 + 32*193) * 4) // 84224 bytes

// ---- scratch (static device arrays; no allocation allowed) ----
__device__ float g_xT[L_DIM * NSEQ];            // x transposed [t][n]
__device__ float g_q[NH * NSEQ * DH];           // [h][n][d]
__device__ float g_k[NH * NSEQ * DH];           // [h][n][d]
__device__ float g_v[NH * NSEQ * L_DIM];        // [h][n][l]

__device__ __forceinline__ float sigf(float x) { return 1.0f / (1.0f + __expf(-x)); }
__device__ __forceinline__ float tanh_fast(float x) { return 2.0f / (1.0f + __expf(-2.0f * x)) - 1.0f; }

__device__ __forceinline__ unsigned long long pack2(float lo, float hi) {
    unsigned long long r;
    asm("mov.b64 %0, {%1, %2};" : "=l"(r) : "f"(lo), "f"(hi));
    return r;
}
__device__ __forceinline__ void unpack2(unsigned long long v, float& lo, float& hi) {
    asm("mov.b64 {%0, %1}, %2;" : "=f"(lo), "=f"(hi) : "l"(v));
}
// d = a*b + c elementwise on packed f32x2 (Blackwell FFMA2)
__device__ __forceinline__ unsigned long long fma2(unsigned long long a, unsigned long long b, unsigned long long c) {
    unsigned long long d;
    asm("fma.rn.f32x2 %0, %1, %2, %3;" : "=l"(d) : "l"(a), "l"(b), "l"(c));
    return d;
}

// ---------------- x transpose: [n][t] -> [t][n] ----------------
__global__ void xT_kernel(const float* __restrict__ x) {
    int i = blockIdx.x * 256 + threadIdx.x;
    if (i < NSEQ * L_DIM) {
        int n = i / L_DIM, t = i - n * L_DIM;
        g_xT[t * NSEQ + n] = x[i];
    }
}

// ---------------- v LSTM (hidden size 1) ----------------
__global__ void v_lstm_kernel(const float* __restrict__ Wih, const float* __restrict__ Whh,
                              const float* __restrict__ bih, const float* __restrict__ bhh) {
    int n = blockIdx.x * 256 + threadIdx.x;
    int h = blockIdx.y;
    if (n >= NSEQ) return;
    float wi[4], wh[4], bb[4];
#pragma unroll
    for (int g = 0; g < 4; g++) {
        wi[g] = Wih[h * 4 + g];
        wh[g] = Whh[h * 4 + g];
        bb[g] = bih[h * 4 + g] + bhh[h * 4 + g];
    }
    float hv = 0.f, c = 0.f;
    float4 buf;
    float* vout = g_v + ((size_t)h * NSEQ + n) * L_DIM;
    for (int t = 0; t < L_DIM; t++) {
        float xv = g_xT[t * NSEQ + n];
        float zi = xv * wi[0] + hv * wh[0] + bb[0];
        float zf = xv * wi[1] + hv * wh[1] + bb[1];
        float zg = xv * wi[2] + hv * wh[2] + bb[2];
        float zo = xv * wi[3] + hv * wh[3] + bb[3];
        c = sigf(zf) * c + sigf(zi) * tanh_fast(zg);
        hv = sigf(zo) * tanh_fast(c);
        ((float*)&buf)[t & 3] = hv;
        if ((t & 3) == 3) *(float4*)(vout + (t - 3)) = buf;
    }
}

// ---------------- q/k LSTM: persistent block, weights in SMEM ----------------
// grid (325, 16): blockIdx.x = group of 32 sequences, blockIdx.y = problem
// (0..7 = q heads, 8..15 = k heads). 256 threads: tid&127 = hidden unit,
// tid>>7 = which half of the 32 sequences (16 each, as 8 f32x2 pairs).
__global__ __launch_bounds__(256, 1) void qk_lstm_kernel(
    const float* __restrict__ qWih, const float* __restrict__ qWhh,
    const float* __restrict__ qbih, const float* __restrict__ qbhh,
    const float* __restrict__ kWih, const float* __restrict__ kWhh,
    const float* __restrict__ kbih, const float* __restrict__ kbhh) {
    extern __shared__ char smem_raw[];
    __half* ws  = (__half*)smem_raw;                          // [kk][hh][gate] 128*128*4 halfs
    float* hbuf = (float*)(smem_raw + 131072);                // 2 buffers [kk][HPAD]
    float* xs   = (float*)(smem_raw + 131072 + 2 * HBUF * 4); // 2 buffers [32]

    const int tid = threadIdx.x;
    const int hh = tid & 127;
    const int sh = tid >> 7;
    const int s_base = sh * 16;
    const int p = blockIdx.y;
    const int head = p & 7;
    const bool is_q = (p < 8);
    const int n0 = blockIdx.x * 32;

    const float* Wih = (is_q ? qWih : kWih) + head * 512;
    const float* Whh = (is_q ? qWhh : kWhh) + (size_t)head * 512 * 128;
    const float* bih = (is_q ? qbih : kbih) + head * 512;
    const float* bhh = (is_q ? qbhh : kbhh) + head * 512;

    // stage recurrent weights (fp16, gate-interleaved for one LDS.64 per kk)
    for (int i = tid; i < 512 * 128; i += 256) {
        int j = i >> 7, kk = i & 127;
        ws[kk * 512 + (j & 127) * 4 + (j >> 7)] = __float2half(Whh[i]);
    }
    for (int i = tid; i < 2 * HBUF; i += 256) hbuf[i] = 0.f;
    if (tid < 32) xs[tid] = g_xT[n0 + tid]; // t = 0

    unsigned long long wihp[4], bsp[4];
#pragma unroll
    for (int g = 0; g < 4; g++) {
        float wv = Wih[g * 128 + hh];
        float bv = bih[g * 128 + hh] + bhh[g * 128 + hh];
        wihp[g] = pack2(wv, wv);
        bsp[g] = pack2(bv, bv);
    }
    float cc[16];
#pragma unroll
    for (int i = 0; i < 16; i++) cc[i] = 0.f;

    __syncthreads();

    int cur = 0;
    for (int t = 0; t < L_DIM; t++) {
        const float* xs_cur = xs + (t & 1) * 32;
        if (tid < 32 && t < L_DIM - 1)
            xs[((t + 1) & 1) * 32 + tid] = g_xT[(t + 1) * NSEQ + n0 + tid];
        const float* hcur = hbuf + cur * HBUF;
        float* hnxt = hbuf + (cur ^ 1) * HBUF;

        unsigned long long acc[4][8];
#pragma unroll
        for (int pp = 0; pp < 8; pp++) {
            unsigned long long xv = *(const unsigned long long*)(xs_cur + s_base + 2 * pp);
#pragma unroll
            for (int g = 0; g < 4; g++) acc[g][pp] = fma2(wihp[g], xv, bsp[g]);
        }

#pragma unroll 4
        for (int kk = 0; kk < 128; kk++) {
            const __half2* wp2 = (const __half2*)(ws + kk * 512 + hh * 4);
            float2 w01 = __half22float2(wp2[0]);
            float2 w23 = __half22float2(wp2[1]);
            unsigned long long wip = pack2(w01.x, w01.x);
            unsigned long long wfp = pack2(w01.y, w01.y);
            unsigned long long wgp = pack2(w23.x, w23.x);
            unsigned long long wop = pack2(w23.y, w23.y);
            const float* hrow = hcur + kk * HPAD + s_base;
#pragma unroll
            for (int pp = 0; pp < 8; pp++) {
                unsigned long long hv = *(const unsigned long long*)(hrow + 2 * pp);
                acc[0][pp] = fma2(wip, hv, acc[0][pp]);
                acc[1][pp] = fma2(wfp, hv, acc[1][pp]);
                acc[2][pp] = fma2(wgp, hv, acc[2][pp]);
                acc[3][pp] = fma2(wop, hv, acc[3][pp]);
            }
        }

#pragma unroll
        for (int pp = 0; pp < 8; pp++) {
            float i0, i1, f0, f1, gg0, gg1, o0, o1;
            unpack2(acc[0][pp], i0, i1);
            unpack2(acc[1][pp], f0, f1);
            unpack2(acc[2][pp], gg0, gg1);
            unpack2(acc[3][pp], o0, o1);
            float c0 = cc[2 * pp], c1 = cc[2 * pp + 1];
            c0 = sigf(f0) * c0 + sigf(i0) * tanh_fast(gg0);
            c1 = sigf(f1) * c1 + sigf(i1) * tanh_fast(gg1);
            float h0 = sigf(o0) * tanh_fast(c0);
            float h1 = sigf(o1) * tanh_fast(c1);
            cc[2 * pp] = c0;
            cc[2 * pp + 1] = c1;
            *(unsigned long long*)(hnxt + hh * HPAD + s_base + 2 * pp) = pack2(h0, h1);
        }
        __syncthreads();
        cur ^= 1;
    }

    float* outbase = (is_q ? g_q : g_k) + (size_t)head * NSEQ * DH;
    const float* hf = hbuf + cur * HBUF;
#pragma unroll
    for (int pp = 0; pp < 8; pp++) {
        int s = s_base + 2 * pp;
        outbase[(size_t)(n0 + s) * DH + hh]     = hf[hh * HPAD + s];
        outbase[(size_t)(n0 + s + 1) * DH + hh] = hf[hh * HPAD + s + 1];
    }
}

// ---------------- attention: scores + leaky + mask + softmax + AV + leaky ----------------
// grid (11, 32, 8): s-tile of 32 rows, batch, head. 256 threads.
__global__ __launch_bounds__(256, 2) void attn_kernel(const float* __restrict__ graph,
                                                      float* __restrict__ out) {
    extern __shared__ char smem_raw[];
    float* qs = (float*)smem_raw;     // [32][129]
    float* sc = qs + 32 * 129;        // [32][336]
    float* kv = sc + 32 * 336;        // [32][193] (k tiles use [32][129])

    const int tid = threadIdx.x;
    const int h = blockIdx.z, b = blockIdx.y;
    const int s0 = blockIdx.x * 32;
    const int nrows = min(32, S_DIM - s0);
    const int w = tid >> 5, lane = tid & 31;

    for (int i = tid; i < nrows * 128; i += 256) {
        int r = i >> 7, d = i & 127;
        qs[r * 129 + d] = g_q[((size_t)h * NSEQ + (size_t)b * S_DIM + s0 + r) * 128 + d];
    }
    __syncthreads();

    // scores: each warp computes 4 consecutive t-columns for all 32 rows (lane = row)
    for (int tk = 0; tk < S_DIM; tk += 32) {
        int tw = min(32, S_DIM - tk);
        for (int i = tid; i < tw * 128; i += 256) {
            int r = i >> 7, d = i & 127;
            kv[r * 129 + d] = g_k[((size_t)h * NSEQ + (size_t)b * S_DIM + tk + r) * 128 + d];
        }
        __syncthreads();
        int si = lane;
        int tl0 = w * 4;
        if (si < nrows && tl0 < tw) {
            float a0 = 0, a1 = 0, a2 = 0, a3 = 0;
            const float* qrow = qs + si * 129;
            const float* k0 = kv + tl0 * 129;
#pragma unroll 4
            for (int d = 0; d < 128; d++) {
                float qv = qrow[d];
                a0 = fmaf(qv, k0[d], a0);
                a1 = fmaf(qv, k0[129 + d], a1);
                a2 = fmaf(qv, k0[258 + d], a2);
                a3 = fmaf(qv, k0[387 + d], a3);
            }
            float av[4] = {a0, a1, a2, a3};
#pragma unroll
            for (int j = 0; j < 4; j++) {
                int t = tk + tl0 + j;
                if (t < S_DIM) {
                    float v = av[j] * 0.08838834764831845f;  // 1/sqrt(128)
                    v = (v >= 0.f) ? v : 0.2f * v;           // leaky
                    float gval = graph[(size_t)t * S_DIM + (s0 + si)];
                    if (s0 + si == t) gval += 1.f;
                    if (gval == 0.f) v += NEG_F;             // mask
                    sc[si * 336 + t] = v;
                }
            }
        }
        __syncthreads();
    }

    // softmax over t, one warp per row
    for (int si = w; si < nrows; si += 8) {
        float* row = sc + si * 336;
        float m = -3.0e38f;
        for (int j = lane; j < S_DIM; j += 32) m = fmaxf(m, row[j]);
#pragma unroll
        for (int o = 16; o; o >>= 1) m = fmaxf(m, __shfl_xor_sync(0xffffffffu, m, o));
        float ssum = 0.f;
        for (int j = lane; j < S_DIM; j += 32) {
            float e = __expf(row[j] - m);
            row[j] = e;
            ssum += e;
        }
#pragma unroll
        for (int o = 16; o; o >>= 1) ssum += __shfl_xor_sync(0xffffffffu, ssum, o);
        float inv = 1.0f / ssum;
        for (int j = lane; j < S_DIM; j += 32) row[j] *= inv;
    }
    __syncthreads();

    // out[si][l] = sum_t attn[si][t] * v[t][l]
    float acc[24];
#pragma unroll
    for (int j = 0; j < 24; j++) acc[j] = 0.f;
    const int si2 = tid >> 3;  // 0..31
    const int lq = tid & 7;    // l = lq + 8*j
    for (int tk = 0; tk < S_DIM; tk += 32) {
        int tw = min(32, S_DIM - tk);
        for (int i = tid; i < tw * 192; i += 256) {
            int r = i / 192, l = i - r * 192;
            kv[r * 193 + l] = g_v[((size_t)h * NSEQ + (size_t)b * S_DIM + tk + r) * 192 + l];
        }
        __syncthreads();
        if (si2 < nrows) {
            for (int t = 0; t < tw; t++) {
                float a = sc[si2 * 336 + tk + t];
                const float* vrow = kv + t * 193 + lq;
#pragma unroll
                for (int j = 0; j < 24; j++) acc[j] = fmaf(a, vrow[8 * j], acc[j]);
            }
        }
        __syncthreads();
    }
    if (si2 < nrows) {
        size_t base = ((size_t)(b * S_DIM + s0 + si2) * 192) * 8 + h;
#pragma unroll
        for (int j = 0; j < 24; j++) {
            float v = acc[j];
            v = (v >= 0.f) ? v : 0.2f * v;  // final leaky
            out[base + (size_t)(lq + 8 * j) * 8] = v;
        }
    }
}

extern "C" void kernel_launch(void* const* d_in, const int* in_sizes, int n_in,
                              void* d_out, int out_size) {
    const float* x     = (const float*)d_in[0];
    const float* graph = (const float*)d_in[1];
    const float* qWih  = (const float*)d_in[2];
    const float* qWhh  = (const float*)d_in[3];
    const float* qbih  = (const float*)d_in[4];
    const float* qbhh  = (const float*)d_in[5];
    const float* kWih  = (const float*)d_in[6];
    const float* kWhh  = (const float*)d_in[7];
    const float* kbih  = (const float*)d_in[8];
    const float* kbhh  = (const float*)d_in[9];
    const float* vWih  = (const float*)d_in[10];
    const float* vWhh  = (const float*)d_in[11];
    const float* vbih  = (const float*)d_in[12];
    const float* vbhh  = (const float*)d_in[13];
    float* out = (float*)d_out;

    cudaFuncSetAttribute(qk_lstm_kernel, cudaFuncAttributeMaxDynamicSharedMemorySize, QK_SMEM);
    cudaFuncSetAttribute(attn_kernel, cudaFuncAttributeMaxDynamicSharedMemorySize, ATTN_SMEM);

    xT_kernel<<<(NSEQ * L_DIM + 255) / 256, 256>>>(x);
    v_lstm_kernel<<<dim3((NSEQ + 255) / 256, NH), 256>>>(vWih, vWhh, vbih, vbhh);
    qk_lstm_kernel<<<dim3(NSEQ / 32, 16), 256, QK_SMEM>>>(qWih, qWhh, qbih, qbhh,
                                                          kWih, kWhh, kbih, kbhh);
    attn_kernel<<<dim3((S_DIM + 31) / 32, B_DIM, NH), 256, ATTN_SMEM>>>(graph, out);
}

// round 2
// speedup vs baseline: 8.5676x; 8.5676x over previous
#include <cuda_runtime.h>
#include <cuda_fp16.h>
#include <math.h>

#define B_DIM 32
#define S_DIM 325
#define L_DIM 192
#define NSEQ (B_DIM * S_DIM)   // 10400
#define DH 128
#define NH 8
#define NEG_F (-1000000000.0f)

// ---- qk HMMA kernel geometry ----
#define MSEQ 64                          // sequences per block
#define WSTR 136                         // half-element stride (128 + 8 pad) for W and h rows
#define XSTR 193
#define NBLK ((NSEQ + MSEQ - 1) / MSEQ)  // 163
#define SM_W_BYTES (512 * WSTR * 2)      // 139264
#define SM_H_BYTES (MSEQ * WSTR * 2)     // 17408
#define SM_X_OFF   (SM_W_BYTES + 2 * SM_H_BYTES)
#define QK_SMEM    (SM_X_OFF + MSEQ * XSTR * 4)   // 223488 bytes

#define ATTN_SMEM ((32*129 + 32*336 + 32*193) * 4) // 84224 bytes

// ---- scratch (static device arrays; no allocation allowed) ----
__device__ float g_xT[L_DIM * NSEQ];            // x transposed [t][n]
__device__ float g_q[NH * NSEQ * DH];           // [h][n][d]
__device__ float g_k[NH * NSEQ * DH];           // [h][n][d]
__device__ float g_v[NH * NSEQ * L_DIM];        // [h][n][l]

__device__ __forceinline__ float sigf(float x) { return 1.0f / (1.0f + __expf(-x)); }
__device__ __forceinline__ float tanh_fast(float x) { return 2.0f / (1.0f + __expf(-2.0f * x)) - 1.0f; }

__device__ __forceinline__ float tanhap(float x) {
    float y; asm("tanh.approx.f32 %0, %1;" : "=f"(y) : "f"(x)); return y;
}
__device__ __forceinline__ float sigap(float x) {
    return fmaf(tanhap(0.5f * x), 0.5f, 0.5f);
}

__device__ __forceinline__ void ldsm4(unsigned& r0, unsigned& r1, unsigned& r2, unsigned& r3,
                                      const void* p) {
    unsigned a = (unsigned)__cvta_generic_to_shared(p);
    asm volatile("ldmatrix.sync.aligned.m8n8.x4.shared.b16 {%0,%1,%2,%3}, [%4];"
                 : "=r"(r0), "=r"(r1), "=r"(r2), "=r"(r3) : "r"(a));
}
__device__ __forceinline__ void mma16816(float* d, const unsigned* a, unsigned b0, unsigned b1) {
    asm volatile("mma.sync.aligned.m16n8k16.row.col.f32.f16.f16.f32 "
                 "{%0,%1,%2,%3}, {%4,%5,%6,%7}, {%8,%9}, {%0,%1,%2,%3};"
                 : "+f"(d[0]), "+f"(d[1]), "+f"(d[2]), "+f"(d[3])
                 : "r"(a[0]), "r"(a[1]), "r"(a[2]), "r"(a[3]), "r"(b0), "r"(b1));
}

// ---------------- x transpose: [n][t] -> [t][n] ----------------
__global__ void xT_kernel(const float* __restrict__ x) {
    int i = blockIdx.x * 256 + threadIdx.x;
    if (i < NSEQ * L_DIM) {
        int n = i / L_DIM, t = i - n * L_DIM;
        g_xT[t * NSEQ + n] = x[i];
    }
}

// ---------------- v LSTM (hidden size 1) ----------------
__global__ void v_lstm_kernel(const float* __restrict__ Wih, const float* __restrict__ Whh,
                              const float* __restrict__ bih, const float* __restrict__ bhh) {
    int n = blockIdx.x * 256 + threadIdx.x;
    int h = blockIdx.y;
    if (n >= NSEQ) return;
    float wi[4], wh[4], bb[4];
#pragma unroll
    for (int g = 0; g < 4; g++) {
        wi[g] = Wih[h * 4 + g];
        wh[g] = Whh[h * 4 + g];
        bb[g] = bih[h * 4 + g] + bhh[h * 4 + g];
    }
    float hv = 0.f, c = 0.f;
    float4 buf;
    float* vout = g_v + ((size_t)h * NSEQ + n) * L_DIM;
    for (int t = 0; t < L_DIM; t++) {
        float xv = g_xT[t * NSEQ + n];
        float zi = xv * wi[0] + hv * wh[0] + bb[0];
        float zf = xv * wi[1] + hv * wh[1] + bb[1];
        float zg = xv * wi[2] + hv * wh[2] + bb[2];
        float zo = xv * wi[3] + hv * wh[3] + bb[3];
        c = sigf(zf) * c + sigf(zi) * tanh_fast(zg);
        hv = sigf(zo) * tanh_fast(c);
        ((float*)&buf)[t & 3] = hv;
        if ((t & 3) == 3) *(float4*)(vout + (t - 3)) = buf;
    }
}

// ---------------- q/k LSTM on tensor cores (HMMA m16n8k16) ----------------
// grid (163, 16): blockIdx.x = group of 64 sequences, blockIdx.y = problem
// (0..7 = q heads, 8..15 = k heads). 256 threads = 8 warps.
// Warp w owns N-columns [w*64, w*64+64) of the permuted gate matrix, where the
// permuted column layout is: col = unit_warp*64 + (gate*2 + unit_half8)*8 + unit%8.
// Thus each accumulator thread holds i,f,g,o for the same (seq, unit) locally.
__global__ __launch_bounds__(256, 1) void qk_lstm_mma(
    const float* __restrict__ x,
    const float* __restrict__ qWih, const float* __restrict__ qWhh,
    const float* __restrict__ qbih, const float* __restrict__ qbhh,
    const float* __restrict__ kWih, const float* __restrict__ kWhh,
    const float* __restrict__ kbih, const float* __restrict__ kbhh) {
    extern __shared__ char sm[];
    __half* ws = (__half*)sm;                       // permuted Whh fp16 [512][WSTR]
    __half* hA = (__half*)(sm + SM_W_BYTES);        // h buffer 0 [64][WSTR]
    __half* hB = (__half*)(sm + SM_W_BYTES + SM_H_BYTES); // h buffer 1
    float* xs = (float*)(sm + SM_X_OFF);            // x [64][XSTR]

    const int tid = threadIdx.x;
    const int warp = tid >> 5, lane = tid & 31;
    const int q4 = lane >> 2, r4 = lane & 3;
    const int p = blockIdx.y, head = p & 7;
    const bool is_q = p < 8;
    const int n0 = blockIdx.x * MSEQ;

    const float* Wih = (is_q ? qWih : kWih) + head * 512;
    const float* Whh = (is_q ? qWhh : kWhh) + (size_t)head * 512 * 128;
    const float* bih = (is_q ? qbih : kbih) + head * 512;
    const float* bhh = (is_q ? qbhh : kbhh) + head * 512;

    // stage permuted recurrent weights (fp16)
    for (int i = tid; i < 512 * 128; i += 256) {
        int row = i >> 7, k = i & 127;
        int g = row >> 7, j = row & 127;
        int pcol = (j >> 4) * 64 + (g * 2 + ((j >> 3) & 1)) * 8 + (j & 7);
        ws[pcol * WSTR + k] = __float2half(Whh[i]);
    }
    // zero h buffer 0
    for (int i = tid; i < MSEQ * WSTR; i += 256) hA[i] = __ushort_as_half((unsigned short)0);
    // stage x for all 192 steps
    for (int i = tid; i < MSEQ * L_DIM; i += 256) {
        int s = i / L_DIM, t = i - s * L_DIM;
        int n = n0 + s;
        xs[s * XSTR + t] = (n < NSEQ) ? x[(size_t)n * L_DIM + t] : 0.f;
    }

    // per-thread input weights / biases for its 16 columns
    float wihr[8][2], br[8][2];
#pragma unroll
    for (int nt = 0; nt < 8; nt++) {
        int g = nt >> 1, uh = nt & 1;
#pragma unroll
        for (int e = 0; e < 2; e++) {
            int row = g * 128 + warp * 16 + uh * 8 + 2 * r4 + e;
            wihr[nt][e] = Wih[row];
            br[nt][e] = bih[row] + bhh[row];
        }
    }

    float cst[4][2][4];
#pragma unroll
    for (int m = 0; m < 4; m++)
#pragma unroll
        for (int uh = 0; uh < 2; uh++)
#pragma unroll
            for (int e = 0; e < 4; e++) cst[m][uh][e] = 0.f;

    // ldmatrix lane address components
    const int grp = lane >> 3, ro = lane & 7;
    const int a_row = (grp & 1) * 8 + ro, a_k = (grp >> 1) * 8;   // A: m0..m3 = (r0-7,k0)(r8-15,k0)(r0-7,k8)(r8-15,k8)
    const int b_row = (grp >> 1) * 8 + ro, b_k = (grp & 1) * 8;   // B: m0..m3 = (n0-7,k0)(n0-7,k8)(n8-15,k0)(n8-15,k8)
    const int wN0 = warp * 64;

    __syncthreads();

    const __half* hc = hA;
    __half* hn = hB;

    for (int t = 0; t < L_DIM; t++) {
        float acc[4][8][4];
        // init accumulators with bias + x_t * Wih
#pragma unroll
        for (int m = 0; m < 4; m++) {
            float x0 = xs[(m * 16 + q4) * XSTR + t];
            float x1 = xs[(m * 16 + q4 + 8) * XSTR + t];
#pragma unroll
            for (int nt = 0; nt < 8; nt++) {
                acc[m][nt][0] = fmaf(x0, wihr[nt][0], br[nt][0]);
                acc[m][nt][1] = fmaf(x0, wihr[nt][1], br[nt][1]);
                acc[m][nt][2] = fmaf(x1, wihr[nt][0], br[nt][0]);
                acc[m][nt][3] = fmaf(x1, wihr[nt][1], br[nt][1]);
            }
        }

        // Z += H @ W^T over K=128
#pragma unroll
        for (int kt = 0; kt < 8; kt++) {
            unsigned a[4][4], b[4][4];
#pragma unroll
            for (int m = 0; m < 4; m++)
                ldsm4(a[m][0], a[m][1], a[m][2], a[m][3],
                      hc + (m * 16 + a_row) * WSTR + kt * 16 + a_k);
#pragma unroll
            for (int j = 0; j < 4; j++)
                ldsm4(b[j][0], b[j][1], b[j][2], b[j][3],
                      ws + (wN0 + j * 16 + b_row) * WSTR + kt * 16 + b_k);
#pragma unroll
            for (int m = 0; m < 4; m++)
#pragma unroll
                for (int j = 0; j < 4; j++) {
                    mma16816(acc[m][2 * j],     a[m], b[j][0], b[j][1]);
                    mma16816(acc[m][2 * j + 1], a[m], b[j][2], b[j][3]);
                }
        }

        // LSTM nonlinearity + h writeback
#pragma unroll
        for (int m = 0; m < 4; m++)
#pragma unroll
            for (int uh = 0; uh < 2; uh++) {
                float h4[4];
#pragma unroll
                for (int e = 0; e < 4; e++) {
                    float zi = acc[m][0 + uh][e];
                    float zf = acc[m][2 + uh][e];
                    float zg = acc[m][4 + uh][e];
                    float zo = acc[m][6 + uh][e];
                    float c = fmaf(sigap(zf), cst[m][uh][e], sigap(zi) * tanhap(zg));
                    cst[m][uh][e] = c;
                    h4[e] = sigap(zo) * tanhap(c);
                }
                int u0 = warp * 16 + uh * 8 + 2 * r4;
                int row0 = m * 16 + q4;
                *(__half2*)(hn + row0 * WSTR + u0)       = __floats2half2_rn(h4[0], h4[1]);
                *(__half2*)(hn + (row0 + 8) * WSTR + u0) = __floats2half2_rn(h4[2], h4[3]);
                if (t == L_DIM - 1) {
                    float* ob = (is_q ? g_q : g_k) + (size_t)head * NSEQ * DH;
                    int n1 = n0 + row0, n2 = n0 + row0 + 8;
                    if (n1 < NSEQ) {
                        ob[(size_t)n1 * DH + u0]     = h4[0];
                        ob[(size_t)n1 * DH + u0 + 1] = h4[1];
                    }
                    if (n2 < NSEQ) {
                        ob[(size_t)n2 * DH + u0]     = h4[2];
                        ob[(size_t)n2 * DH + u0 + 1] = h4[3];
                    }
                }
            }
        __syncthreads();
        { __half* tmp = (__half*)hc; hc = hn; hn = tmp; }
    }
}

// ---------------- attention: scores + leaky + mask + softmax + AV + leaky ----------------
// grid (11, 32, 8): s-tile of 32 rows, batch, head. 256 threads.
__global__ __launch_bounds__(256, 2) void attn_kernel(const float* __restrict__ graph,
                                                      float* __restrict__ out) {
    extern __shared__ char smem_raw[];
    float* qs = (float*)smem_raw;     // [32][129]
    float* sc = qs + 32 * 129;        // [32][336]
    float* kv = sc + 32 * 336;        // [32][193] (k tiles use [32][129])

    const int tid = threadIdx.x;
    const int h = blockIdx.z, b = blockIdx.y;
    const int s0 = blockIdx.x * 32;
    const int nrows = min(32, S_DIM - s0);
    const int w = tid >> 5, lane = tid & 31;

    for (int i = tid; i < nrows * 128; i += 256) {
        int r = i >> 7, d = i & 127;
        qs[r * 129 + d] = g_q[((size_t)h * NSEQ + (size_t)b * S_DIM + s0 + r) * 128 + d];
    }
    __syncthreads();

    for (int tk = 0; tk < S_DIM; tk += 32) {
        int tw = min(32, S_DIM - tk);
        for (int i = tid; i < tw * 128; i += 256) {
            int r = i >> 7, d = i & 127;
            kv[r * 129 + d] = g_k[((size_t)h * NSEQ + (size_t)b * S_DIM + tk + r) * 128 + d];
        }
        __syncthreads();
        int si = lane;
        int tl0 = w * 4;
        if (si < nrows && tl0 < tw) {
            float a0 = 0, a1 = 0, a2 = 0, a3 = 0;
            const float* qrow = qs + si * 129;
            const float* k0 = kv + tl0 * 129;
#pragma unroll 4
            for (int d = 0; d < 128; d++) {
                float qv = qrow[d];
                a0 = fmaf(qv, k0[d], a0);
                a1 = fmaf(qv, k0[129 + d], a1);
                a2 = fmaf(qv, k0[258 + d], a2);
                a3 = fmaf(qv, k0[387 + d], a3);
            }
            float av[4] = {a0, a1, a2, a3};
#pragma unroll
            for (int j = 0; j < 4; j++) {
                int t = tk + tl0 + j;
                if (t < S_DIM) {
                    float v = av[j] * 0.08838834764831845f;  // 1/sqrt(128)
                    v = (v >= 0.f) ? v : 0.2f * v;           // leaky
                    float gval = graph[(size_t)t * S_DIM + (s0 + si)];
                    if (s0 + si == t) gval += 1.f;
                    if (gval == 0.f) v += NEG_F;             // mask
                    sc[si * 336 + t] = v;
                }
            }
        }
        __syncthreads();
    }

    for (int si = w; si < nrows; si += 8) {
        float* row = sc + si * 336;
        float m = -3.0e38f;
        for (int j = lane; j < S_DIM; j += 32) m = fmaxf(m, row[j]);
#pragma unroll
        for (int o = 16; o; o >>= 1) m = fmaxf(m, __shfl_xor_sync(0xffffffffu, m, o));
        float ssum = 0.f;
        for (int j = lane; j < S_DIM; j += 32) {
            float e = __expf(row[j] - m);
            row[j] = e;
            ssum += e;
        }
#pragma unroll
        for (int o = 16; o; o >>= 1) ssum += __shfl_xor_sync(0xffffffffu, ssum, o);
        float inv = 1.0f / ssum;
        for (int j = lane; j < S_DIM; j += 32) row[j] *= inv;
    }
    __syncthreads();

    float acc[24];
#pragma unroll
    for (int j = 0; j < 24; j++) acc[j] = 0.f;
    const int si2 = tid >> 3;
    const int lq = tid & 7;
    for (int tk = 0; tk < S_DIM; tk += 32) {
        int tw = min(32, S_DIM - tk);
        for (int i = tid; i < tw * 192; i += 256) {
            int r = i / 192, l = i - r * 192;
            kv[r * 193 + l] = g_v[((size_t)h * NSEQ + (size_t)b * S_DIM + tk + r) * 192 + l];
        }
        __syncthreads();
        if (si2 < nrows) {
            for (int t = 0; t < tw; t++) {
                float a = sc[si2 * 336 + tk + t];
                const float* vrow = kv + t * 193 + lq;
#pragma unroll
                for (int j = 0; j < 24; j++) acc[j] = fmaf(a, vrow[8 * j], acc[j]);
            }
        }
        __syncthreads();
    }
    if (si2 < nrows) {
        size_t base = ((size_t)(b * S_DIM + s0 + si2) * 192) * 8 + h;
#pragma unroll
        for (int j = 0; j < 24; j++) {
            float v = acc[j];
            v = (v >= 0.f) ? v : 0.2f * v;  // final leaky
            out[base + (size_t)(lq + 8 * j) * 8] = v;
        }
    }
}

extern "C" void kernel_launch(void* const* d_in, const int* in_sizes, int n_in,
                              void* d_out, int out_size) {
    const float* x     = (const float*)d_in[0];
    const float* graph = (const float*)d_in[1];
    const float* qWih  = (const float*)d_in[2];
    const float* qWhh  = (const float*)d_in[3];
    const float* qbih  = (const float*)d_in[4];
    const float* qbhh  = (const float*)d_in[5];
    const float* kWih  = (const float*)d_in[6];
    const float* kWhh  = (const float*)d_in[7];
    const float* kbih  = (const float*)d_in[8];
    const float* kbhh  = (const float*)d_in[9];
    const float* vWih  = (const float*)d_in[10];
    const float* vWhh  = (const float*)d_in[11];
    const float* vbih  = (const float*)d_in[12];
    const float* vbhh  = (const float*)d_in[13];
    float* out = (float*)d_out;

    cudaFuncSetAttribute(qk_lstm_mma, cudaFuncAttributeMaxDynamicSharedMemorySize, QK_SMEM);
    cudaFuncSetAttribute(attn_kernel, cudaFuncAttributeMaxDynamicSharedMemorySize, ATTN_SMEM);

    xT_kernel<<<(NSEQ * L_DIM + 255) / 256, 256>>>(x);
    v_lstm_kernel<<<dim3((NSEQ + 255) / 256, NH), 256>>>(vWih, vWhh, vbih, vbhh);
    qk_lstm_mma<<<dim3(NBLK, 16), 256, QK_SMEM>>>(x, qWih, qWhh, qbih, qbhh,
                                                  kWih, kWhh, kbih, kbhh);
    attn_kernel<<<dim3((S_DIM + 31) / 32, B_DIM, NH), 256, ATTN_SMEM>>>(graph, out);
}

// round 4
// speedup vs baseline: 8.9482x; 1.0444x over previous
#include <cuda_runtime.h>
#include <cuda_fp16.h>
#include <math.h>

#define B_DIM 32
#define S_DIM 325
#define L_DIM 192
#define NSEQ (B_DIM * S_DIM)   // 10400
#define DH 128
#define NH 8
#define NEG_F (-1000000000.0f)

// ---- qk HMMA kernel geometry ----
#define MSEQ 64                          // sequences per block
#define WSTR 136                         // half-element stride (128 + 8 pad)
#define XSTR 193
#define NBLK ((NSEQ + MSEQ - 1) / MSEQ)  // 163
#define SM_W_BYTES (512 * WSTR * 2)      // 139264
#define SM_H_BYTES (MSEQ * WSTR * 2)     // 17408
#define SM_X_OFF   (SM_W_BYTES + 2 * SM_H_BYTES)       // 174080
#define SM_MBAR_OFF (SM_X_OFF + MSEQ * XSTR * 4)       // 223488
#define QK_SMEM    (SM_MBAR_OFF + 64)                  // 223552 bytes

#define ATTN_SMEM ((32*129 + 32*336 + 32*193) * 4) // 84224 bytes

// ---- scratch (static device arrays; no allocation allowed) ----
__device__ float g_xT[L_DIM * NSEQ];            // x transposed [t][n]
__device__ float g_q[NH * NSEQ * DH];           // [h][n][d]
__device__ float g_k[NH * NSEQ * DH];           // [h][n][d]
__device__ float g_v[NH * NSEQ * L_DIM];        // [h][n][l]

__device__ __forceinline__ float sigf(float x) { return 1.0f / (1.0f + __expf(-x)); }
__device__ __forceinline__ float tanh_fast(float x) { return 2.0f / (1.0f + __expf(-2.0f * x)) - 1.0f; }

__device__ __forceinline__ __half2 tanh2(__half2 x) {
    unsigned y, xi = *(unsigned*)&x;
    asm("tanh.approx.f16x2 %0, %1;" : "=r"(y) : "r"(xi));
    return *(__half2*)&y;
}

__device__ __forceinline__ void ldsm4(unsigned& r0, unsigned& r1, unsigned& r2, unsigned& r3,
                                      const void* p) {
    unsigned a = (unsigned)__cvta_generic_to_shared(p);
    asm volatile("ldmatrix.sync.aligned.m8n8.x4.shared.b16 {%0,%1,%2,%3}, [%4];"
                 : "=r"(r0), "=r"(r1), "=r"(r2), "=r"(r3) : "r"(a));
}
__device__ __forceinline__ void mma16816(float* d, const unsigned* a, unsigned b0, unsigned b1) {
    asm volatile("mma.sync.aligned.m16n8k16.row.col.f32.f16.f16.f32 "
                 "{%0,%1,%2,%3}, {%4,%5,%6,%7}, {%8,%9}, {%0,%1,%2,%3};"
                 : "+f"(d[0]), "+f"(d[1]), "+f"(d[2]), "+f"(d[3])
                 : "r"(a[0]), "r"(a[1]), "r"(a[2]), "r"(a[3]), "r"(b0), "r"(b1));
}

__device__ __forceinline__ void mbar_init(unsigned addr, unsigned cnt) {
    asm volatile("mbarrier.init.shared.b64 [%0], %1;" :: "r"(addr), "r"(cnt) : "memory");
}
__device__ __forceinline__ void mbar_arrive(unsigned addr) {
    asm volatile("mbarrier.arrive.shared.b64 _, [%0];" :: "r"(addr) : "memory");
}
__device__ __forceinline__ void mbar_wait(unsigned addr, unsigned parity) {
    asm volatile(
        "{\n\t"
        ".reg .pred P;\n"
        "WAIT_%=:\n\t"
        "mbarrier.try_wait.parity.acquire.cta.shared::cta.b64 P, [%0], %1;\n\t"
        "@!P bra WAIT_%=;\n\t"
        "}"
        :: "r"(addr), "r"(parity) : "memory");
}

// ---------------- x transpose: [n][t] -> [t][n] ----------------
__global__ void xT_kernel(const float* __restrict__ x) {
    int i = blockIdx.x * 256 + threadIdx.x;
    if (i < NSEQ * L_DIM) {
        int n = i / L_DIM, t = i - n * L_DIM;
        g_xT[t * NSEQ + n] = x[i];
    }
}

// ---------------- v LSTM (hidden size 1) ----------------
__global__ void v_lstm_kernel(const float* __restrict__ Wih, const float* __restrict__ Whh,
                              const float* __restrict__ bih, const float* __restrict__ bhh) {
    int n = blockIdx.x * 256 + threadIdx.x;
    int h = blockIdx.y;
    if (n >= NSEQ) return;
    float wi[4], wh[4], bb[4];
#pragma unroll
    for (int g = 0; g < 4; g++) {
        wi[g] = Wih[h * 4 + g];
        wh[g] = Whh[h * 4 + g];
        bb[g] = bih[h * 4 + g] + bhh[h * 4 + g];
    }
    float hv = 0.f, c = 0.f;
    float4 buf;
    float* vout = g_v + ((size_t)h * NSEQ + n) * L_DIM;
    for (int t = 0; t < L_DIM; t++) {
        float xv = g_xT[t * NSEQ + n];
        float zi = xv * wi[0] + hv * wh[0] + bb[0];
        float zf = xv * wi[1] + hv * wh[1] + bb[1];
        float zg = xv * wi[2] + hv * wh[2] + bb[2];
        float zo = xv * wi[3] + hv * wh[3] + bb[3];
        c = sigf(zf) * c + sigf(zi) * tanh_fast(zg);
        hv = sigf(zo) * tanh_fast(c);
        ((float*)&buf)[t & 3] = hv;
        if ((t & 3) == 3) *(float4*)(vout + (t - 3)) = buf;
    }
}

// ---------------- q/k LSTM on tensor cores (HMMA m16n8k16) ----------------
// grid (163, 16). 256 threads = 8 warps. Warp w owns permuted gate N-columns
// [w*64, w*64+64) == hidden units [16w, 16w+16) x 4 gates, i.e. exactly K-chunk
// w of the NEXT step's reduction. Per-step global barrier replaced by 8
// mbarriers (producer warp w arrives after writing its h chunk; consumers wait
// per chunk, consuming in order (w+c)&7 so the own chunk needs no wait).
__global__ __launch_bounds__(256, 1) void qk_lstm_mma(
    const float* __restrict__ x,
    const float* __restrict__ qWih, const float* __restrict__ qWhh,
    const float* __restrict__ qbih, const float* __restrict__ qbhh,
    const float* __restrict__ kWih, const float* __restrict__ kWhh,
    const float* __restrict__ kbih, const float* __restrict__ kbhh) {
    extern __shared__ char sm[];
    __half* ws = (__half*)sm;                       // permuted Whh fp16 [512][WSTR]
    __half* hA = (__half*)(sm + SM_W_BYTES);        // h buffer 0 [64][WSTR]
    __half* hB = (__half*)(sm + SM_W_BYTES + SM_H_BYTES); // h buffer 1
    float* xs = (float*)(sm + SM_X_OFF);            // x [64][XSTR]
    const unsigned mbar0 = (unsigned)__cvta_generic_to_shared(sm + SM_MBAR_OFF);

    const int tid = threadIdx.x;
    const int warp = tid >> 5, lane = tid & 31;
    const int q4 = lane >> 2, r4 = lane & 3;
    const int p = blockIdx.y, head = p & 7;
    const bool is_q = p < 8;
    const int n0 = blockIdx.x * MSEQ;

    const float* Wih = (is_q ? qWih : kWih) + head * 512;
    const float* Whh = (is_q ? qWhh : kWhh) + (size_t)head * 512 * 128;
    const float* bih = (is_q ? qbih : kbih) + head * 512;
    const float* bhh = (is_q ? qbhh : kbhh) + head * 512;

    // stage permuted recurrent weights (fp16)
    for (int i = tid; i < 512 * 128; i += 256) {
        int row = i >> 7, k = i & 127;
        int g = row >> 7, j = row & 127;
        int pcol = (j >> 4) * 64 + (g * 2 + ((j >> 3) & 1)) * 8 + (j & 7);
        ws[pcol * WSTR + k] = __float2half(Whh[i]);
    }
    // zero h buffer 0
    for (int i = tid; i < MSEQ * WSTR; i += 256) hA[i] = __ushort_as_half((unsigned short)0);
    // stage x for all 192 steps
    for (int i = tid; i < MSEQ * L_DIM; i += 256) {
        int s = i / L_DIM, t = i - s * L_DIM;
        int n = n0 + s;
        xs[s * XSTR + t] = (n < NSEQ) ? x[(size_t)n * L_DIM + t] : 0.f;
    }
    if (tid < 8) mbar_init(mbar0 + tid * 8, 1);

    // per-thread input weights / biases for its 16 columns
    float wihr[8][2], br[8][2];
#pragma unroll
    for (int nt = 0; nt < 8; nt++) {
        int g = nt >> 1, uh = nt & 1;
#pragma unroll
        for (int e = 0; e < 2; e++) {
            int row = g * 128 + warp * 16 + uh * 8 + 2 * r4 + e;
            wihr[nt][e] = Wih[row];
            br[nt][e] = bih[row] + bhh[row];
        }
    }

    __half2 c2[4][2][2];
#pragma unroll
    for (int m = 0; m < 4; m++)
#pragma unroll
        for (int uh = 0; uh < 2; uh++)
#pragma unroll
            for (int pr = 0; pr < 2; pr++) c2[m][uh][pr] = __floats2half2_rn(0.f, 0.f);

    // ldmatrix lane address components
    const int grp = lane >> 3, ro = lane & 7;
    const int a_row = (grp & 1) * 8 + ro, a_k = (grp >> 1) * 8;
    const int b_row = (grp >> 1) * 8 + ro, b_k = (grp & 1) * 8;
    const int wN0 = warp * 64;
    const int u0 = warp * 16 + 2 * r4;  // + uh*8 later
    const __half2 H05 = __floats2half2_rn(0.5f, 0.5f);

    __syncthreads();

    const __half* hc = hA;
    __half* hn = hB;

    for (int t = 0; t < L_DIM; t++) {
        float acc[4][8][4];
        // init accumulators with bias + x_t * Wih
#pragma unroll
        for (int m = 0; m < 4; m++) {
            float x0 = xs[(m * 16 + q4) * XSTR + t];
            float x1 = xs[(m * 16 + q4 + 8) * XSTR + t];
#pragma unroll
            for (int nt = 0; nt < 8; nt++) {
                acc[m][nt][0] = fmaf(x0, wihr[nt][0], br[nt][0]);
                acc[m][nt][1] = fmaf(x0, wihr[nt][1], br[nt][1]);
                acc[m][nt][2] = fmaf(x1, wihr[nt][0], br[nt][0]);
                acc[m][nt][3] = fmaf(x1, wihr[nt][1], br[nt][1]);
            }
        }

        // Z += H @ W^T over K=128, consuming chunks own-first
        const unsigned par = (unsigned)((t - 1) & 1);
#pragma unroll
        for (int c = 0; c < 8; c++) {
            const int kt = (warp + c) & 7;
            if (c > 0 && t > 0) mbar_wait(mbar0 + kt * 8, par);
            unsigned a[4][4], b[4][4];
#pragma unroll
            for (int m = 0; m < 4; m++)
                ldsm4(a[m][0], a[m][1], a[m][2], a[m][3],
                      hc + (m * 16 + a_row) * WSTR + kt * 16 + a_k);
#pragma unroll
            for (int j = 0; j < 4; j++)
                ldsm4(b[j][0], b[j][1], b[j][2], b[j][3],
                      ws + (wN0 + j * 16 + b_row) * WSTR + kt * 16 + b_k);
#pragma unroll
            for (int m = 0; m < 4; m++)
#pragma unroll
                for (int j = 0; j < 4; j++) {
                    mma16816(acc[m][2 * j],     a[m], b[j][0], b[j][1]);
                    mma16816(acc[m][2 * j + 1], a[m], b[j][2], b[j][3]);
                }
        }

        // LSTM nonlinearity in f16x2 + h writeback (only our own unit chunk)
#pragma unroll
        for (int m = 0; m < 4; m++)
#pragma unroll
            for (int uh = 0; uh < 2; uh++) {
#pragma unroll
                for (int pr = 0; pr < 2; pr++) {
                    const int e = 2 * pr;
                    __half2 zi = __floats2half2_rn(acc[m][0 + uh][e], acc[m][0 + uh][e + 1]);
                    __half2 zf = __floats2half2_rn(acc[m][2 + uh][e], acc[m][2 + uh][e + 1]);
                    __half2 zg = __floats2half2_rn(acc[m][4 + uh][e], acc[m][4 + uh][e + 1]);
                    __half2 zo = __floats2half2_rn(acc[m][6 + uh][e], acc[m][6 + uh][e + 1]);
                    __half2 si = __hfma2(tanh2(__hmul2(zi, H05)), H05, H05);
                    __half2 sf = __hfma2(tanh2(__hmul2(zf, H05)), H05, H05);
                    __half2 so = __hfma2(tanh2(__hmul2(zo, H05)), H05, H05);
                    __half2 tg = tanh2(zg);
                    __half2 cc = __hfma2(sf, c2[m][uh][pr], __hmul2(si, tg));
                    c2[m][uh][pr] = cc;
                    __half2 h2 = __hmul2(so, tanh2(cc));
                    const int row = m * 16 + q4 + pr * 8;
                    *(__half2*)(hn + row * WSTR + u0 + uh * 8) = h2;
                    if (t == L_DIM - 1) {
                        float* ob = (is_q ? g_q : g_k) + (size_t)head * NSEQ * DH;
                        int n1 = n0 + row;
                        if (n1 < NSEQ) {
                            float2 f = __half22float2(h2);
                            ob[(size_t)n1 * DH + u0 + uh * 8]     = f.x;
                            ob[(size_t)n1 * DH + u0 + uh * 8 + 1] = f.y;
                        }
                    }
                }
            }
        __syncwarp();
        if (lane == 0) mbar_arrive(mbar0 + warp * 8);
        { __half* tmp = (__half*)hc; hc = hn; hn = tmp; }
    }
}

// ---------------- attention: scores + leaky + mask + softmax + AV + leaky ----------------
__global__ __launch_bounds__(256, 2) void attn_kernel(const float* __restrict__ graph,
                                                      float* __restrict__ out) {
    extern __shared__ char smem_raw[];
    float* qs = (float*)smem_raw;     // [32][129]
    float* sc = qs + 32 * 129;        // [32][336]
    float* kv = sc + 32 * 336;        // [32][193]

    const int tid = threadIdx.x;
    const int h = blockIdx.z, b = blockIdx.y;
    const int s0 = blockIdx.x * 32;
    const int nrows = min(32, S_DIM - s0);
    const int w = tid >> 5, lane = tid & 31;

    for (int i = tid; i < nrows * 128; i += 256) {
        int r = i >> 7, d = i & 127;
        qs[r * 129 + d] = g_q[((size_t)h * NSEQ + (size_t)b * S_DIM + s0 + r) * 128 + d];
    }
    __syncthreads();

    for (int tk = 0; tk < S_DIM; tk += 32) {
        int tw = min(32, S_DIM - tk);
        for (int i = tid; i < tw * 128; i += 256) {
            int r = i >> 7, d = i & 127;
            kv[r * 129 + d] = g_k[((size_t)h * NSEQ + (size_t)b * S_DIM + tk + r) * 128 + d];
        }
        __syncthreads();
        int si = lane;
        int tl0 = w * 4;
        if (si < nrows && tl0 < tw) {
            float a0 = 0, a1 = 0, a2 = 0, a3 = 0;
            const float* qrow = qs + si * 129;
            const float* k0 = kv + tl0 * 129;
#pragma unroll 4
            for (int d = 0; d < 128; d++) {
                float qv = qrow[d];
                a0 = fmaf(qv, k0[d], a0);
                a1 = fmaf(qv, k0[129 + d], a1);
                a2 = fmaf(qv, k0[258 + d], a2);
                a3 = fmaf(qv, k0[387 + d], a3);
            }
            float av[4] = {a0, a1, a2, a3};
#pragma unroll
            for (int j = 0; j < 4; j++) {
                int t = tk + tl0 + j;
                if (t < S_DIM) {
                    float v = av[j] * 0.08838834764831845f;  // 1/sqrt(128)
                    v = (v >= 0.f) ? v : 0.2f * v;           // leaky
                    float gval = graph[(size_t)t * S_DIM + (s0 + si)];
                    if (s0 + si == t) gval += 1.f;
                    if (gval == 0.f) v += NEG_F;             // mask
                    sc[si * 336 + t] = v;
                }
            }
        }
        __syncthreads();
    }

    for (int si = w; si < nrows; si += 8) {
        float* row = sc + si * 336;
        float m = -3.0e38f;
        for (int j = lane; j < S_DIM; j += 32) m = fmaxf(m, row[j]);
#pragma unroll
        for (int o = 16; o; o >>= 1) m = fmaxf(m, __shfl_xor_sync(0xffffffffu, m, o));
        float ssum = 0.f;
        for (int j = lane; j < S_DIM; j += 32) {
            float e = __expf(row[j] - m);
            row[j] = e;
            ssum += e;
        }
#pragma unroll
        for (int o = 16; o; o >>= 1) ssum += __shfl_xor_sync(0xffffffffu, ssum, o);
        float inv = 1.0f / ssum;
        for (int j = lane; j < S_DIM; j += 32) row[j] *= inv;
    }
    __syncthreads();

    float acc[24];
#pragma unroll
    for (int j = 0; j < 24; j++) acc[j] = 0.f;
    const int si2 = tid >> 3;
    const int lq = tid & 7;
    for (int tk = 0; tk < S_DIM; tk += 32) {
        int tw = min(32, S_DIM - tk);
        for (int i = tid; i < tw * 192; i += 256) {
            int r = i / 192, l = i - r * 192;
            kv[r * 193 + l] = g_v[((size_t)h * NSEQ + (size_t)b * S_DIM + tk + r) * 192 + l];
        }
        __syncthreads();
        if (si2 < nrows) {
            for (int t = 0; t < tw; t++) {
                float a = sc[si2 * 336 + tk + t];
                const float* vrow = kv + t * 193 + lq;
#pragma unroll
                for (int j = 0; j < 24; j++) acc[j] = fmaf(a, vrow[8 * j], acc[j]);
            }
        }
        __syncthreads();
    }
    if (si2 < nrows) {
        size_t base = ((size_t)(b * S_DIM + s0 + si2) * 192) * 8 + h;
#pragma unroll
        for (int j = 0; j < 24; j++) {
            float v = acc[j];
            v = (v >= 0.f) ? v : 0.2f * v;  // final leaky
            out[base + (size_t)(lq + 8 * j) * 8] = v;
        }
    }
}

extern "C" void kernel_launch(void* const* d_in, const int* in_sizes, int n_in,
                              void* d_out, int out_size) {
    const float* x     = (const float*)d_in[0];
    const float* graph = (const float*)d_in[1];
    const float* qWih  = (const float*)d_in[2];
    const float* qWhh  = (const float*)d_in[3];
    const float* qbih  = (const float*)d_in[4];
    const float* qbhh  = (const float*)d_in[5];
    const float* kWih  = (const float*)d_in[6];
    const float* kWhh  = (const float*)d_in[7];
    const float* kbih  = (const float*)d_in[8];
    const float* kbhh  = (const float*)d_in[9];
    const float* vWih  = (const float*)d_in[10];
    const float* vWhh  = (const float*)d_in[11];
    const float* vbih  = (const float*)d_in[12];
    const float* vbhh  = (const float*)d_in[13];
    float* out = (float*)d_out;

    cudaFuncSetAttribute(qk_lstm_mma, cudaFuncAttributeMaxDynamicSharedMemorySize, QK_SMEM);
    cudaFuncSetAttribute(attn_kernel, cudaFuncAttributeMaxDynamicSharedMemorySize, ATTN_SMEM);

    xT_kernel<<<(NSEQ * L_DIM + 255) / 256, 256>>>(x);
    v_lstm_kernel<<<dim3((NSEQ + 255) / 256, NH), 256>>>(vWih, vWhh, vbih, vbhh);
    qk_lstm_mma<<<dim3(NBLK, 16), 256, QK_SMEM>>>(x, qWih, qWhh, qbih, qbhh,
                                                  kWih, kWhh, kbih, kbhh);
    attn_kernel<<<dim3((S_DIM + 31) / 32, B_DIM, NH), 256, ATTN_SMEM>>>(graph, out);
}